// round 5
// baseline (speedup 1.0000x reference)
#include <cuda_runtime.h>

// LIF scan with speculative FADD chain + exact renewal select.
//
// Group of GL=8 steps: A-chain A_i = A_{i-1}+x_i (pure FADD, 4cyc/step) is
// the only thing on the serial critical path. First-crossing one-hot weights
// (exact 0/1 floats) select between A_8 (no spike: exact sequential sum) and
// E_k = precomputed exact exit of a restart at position k (renewal property:
// post-spike trajectory is independent of history). All selects are exact.
//
// 64 blocks = 16 batches x 4 neuron-quarters (16 neurons). 4 warps, one per
// SMSP: W0 chain, W1 E-helpers, W2 rerun (exact per-step S for outputs),
// W3 drain (coalesced STG.128) + x staging. 5-stage pipeline, 1 bar/tile.

#define NB 16
#define NS 256
#define NH 128
#define NN 64
#define NPB 16
#define GL 8
#define NG 16                       // groups per tile (NH/GL)
#define RS 132
#define TOTE ((long long)NB * NS * NN * NH)

// exact reference step on pre-reset value S (proven exact in R4)
#define STEPX(S, XV, TH) do {                                               \
    float f_;                                                               \
    asm("set.le.f32.f32 %0, %1, %2;" : "=f"(f_) : "f"(S), "f"(TH));         \
    asm("fma.rn.f32 %0, %1, %2, %3;" : "=f"(S) : "f"(S), "f"(f_), "f"(XV)); \
} while (0)

// ---------- helper warp: E_k tables for one tile (x-only dependent) --------
__device__ __forceinline__ void do_helpers(const float* __restrict__ xrow,
                                           float* __restrict__ Edst,
                                           const float* __restrict__ thr_s,
                                           int lane)
{
    const int par = lane >> 4;
    const int nl  = lane & 15;
    const float th = thr_s[nl];
    #pragma unroll
    for (int gg = 0; gg < 8; ++gg) {
        const int g = gg * 2 + par;
        float x[8];
        *(float4*)&x[0] = *(const float4*)(xrow + g * 8);
        *(float4*)&x[4] = *(const float4*)(xrow + g * 8 + 4);
        float E[8];
        E[7] = x[7];                       // restart at last transition
        #pragma unroll
        for (int k = 7; k >= 1; --k) {     // E_k: S_k = x_k, run transitions k+1..8
            float S = x[k - 1];
            #pragma unroll
            for (int i = k; i < 8; ++i) STEPX(S, x[i], th);
            E[k - 1] = S;
        }
        #pragma unroll
        for (int k = 0; k < 8; ++k)
            Edst[(g * GL + k) * NPB + nl] = E[k];
    }
}

// ---------- rerun warp: exact per-step S from group-entry values -----------
__device__ __forceinline__ void do_rerun(const float* __restrict__ xrow,
                                         const float* __restrict__ bsrc,
                                         float* __restrict__ sdst,
                                         const float* __restrict__ thr_s,
                                         int lane)
{
    const int par = lane >> 4;
    const int nl  = lane & 15;
    const float th = thr_s[nl];
    #pragma unroll
    for (int gg = 0; gg < 8; ++gg) {
        const int g = gg * 2 + par;
        float S = bsrc[g * NPB + nl];
        float x[8], o[8];
        *(float4*)&x[0] = *(const float4*)(xrow + g * 8);
        *(float4*)&x[4] = *(const float4*)(xrow + g * 8 + 4);
        #pragma unroll
        for (int i = 0; i < 8; ++i) { STEPX(S, x[i], th); o[i] = S; }
        *(float4*)&sdst[nl * RS + g * 8]     = *(float4*)&o[0];
        *(float4*)&sdst[nl * RS + g * 8 + 4] = *(float4*)&o[4];
    }
}

// ---------- drain warp: coalesced output of one tile -----------------------
__device__ __forceinline__ void do_drain(int b, int q, int s,
                                         const float* __restrict__ ssrc,
                                         const float* __restrict__ thr_s,
                                         float* __restrict__ outbuf, int lane)
{
    float* ob = outbuf + (((long long)b * NS + s) * NN + q * NPB) * NH;
    float* sb = ob + TOTE;
    #pragma unroll
    for (int n = 0; n < NPB; ++n) {
        float th = thr_s[n];
        float4 v = *(const float4*)(ssrc + n * RS + lane * 4);   // LDS.128
        bool p0 = v.x > th, p1 = v.y > th, p2 = v.z > th, p3 = v.w > th;
        float4 o, sp;
        o.x = p0 ? v.x : 0.0f;  sp.x = p0 ? 1.0f : 0.0f;
        o.y = p1 ? v.y : 0.0f;  sp.y = p1 ? 1.0f : 0.0f;
        o.z = p2 ? v.z : 0.0f;  sp.z = p2 ? 1.0f : 0.0f;
        o.w = p3 ? v.w : 0.0f;  sp.w = p3 ? 1.0f : 0.0f;
        *(float4*)(ob + n * NH + lane * 4) = o;                  // STG.128
        *(float4*)(sb + n * NH + lane * 4) = sp;
    }
}

__global__ __launch_bounds__(128, 1)
void lif_kernel(const float* __restrict__ inputs,
                const float* __restrict__ threshes,
                const float* __restrict__ acc0,
                float* __restrict__ outbuf)
{
    __shared__ float xs[4][NH];              // 2 KB  (4-deep: t-1,t,t+1,t+2)
    __shared__ float Et[2][NG * GL * NPB];   // 16 KB E tables
    __shared__ float sbuf[2][NPB * RS];      // 16.9 KB per-step S
    __shared__ float bnd[2][NG * NPB];       // 2 KB group-entry values
    __shared__ float thr_s[NPB];

    const int b    = blockIdx.x >> 2;
    const int q    = blockIdx.x & 3;
    const int tid  = threadIdx.x;
    const int wid  = tid >> 5;
    const int lane = tid & 31;
    const float* xb = inputs + (long long)b * NS * NH;

    // ---- prologue tick 1: stage x(0), thresholds ----
    if (wid == 3) {
        *(float4*)&xs[0][lane * 4] = *(const float4*)(xb + lane * 4);
        if (lane < NPB) thr_s[lane] = threshes[q * NPB + lane];
    }
    __syncthreads();
    // ---- prologue tick 2: E(0); stage x(1) ----
    if (wid == 1) do_helpers(xs[0], Et[0], thr_s, lane);
    if (wid == 3) *(float4*)&xs[1][lane * 4] = *(const float4*)(xb + NH + lane * 4);
    __syncthreads();

    // chain state (wid 0)
    const int   nl = lane & 15;
    const float th = (wid == 0) ? thr_s[nl] : 0.0f;
    float S = (wid == 0) ? acc0[b * NN + q * NPB + nl] : 0.0f;

    for (int t = 0; t <= NS + 1; ++t) {
        if (wid == 0 && t < NS) {
            // ---------------- chain: 16 groups of 8 ----------------
            const float* __restrict__ Ecur = Et[t & 1];
            const float* __restrict__ xr   = xs[t & 3];
            const float* __restrict__ xr2  = xs[(t + 1) & 3];
            float* __restrict__       bdst = bnd[t & 1];

            float xg[8], xn[8], ex[8], en[8];
            *(float4*)&xg[0] = *(const float4*)(xr);
            *(float4*)&xg[4] = *(const float4*)(xr + 4);
            #pragma unroll
            for (int k = 0; k < 8; ++k) ex[k] = Ecur[k * NPB + nl];

            #pragma unroll
            for (int g = 0; g < NG; ++g) {
                if (lane < NPB) bdst[g * NPB + nl] = S;   // group entry
                // prefetch next group's x (cross-tile ok: x(t+1) staged)
                const float* xsrc = (g < NG - 1) ? (xr + (g + 1) * 8) : xr2;
                if (t < NS - 1 || g < NG - 1) {
                    *(float4*)&xn[0] = *(const float4*)(xsrc);
                    *(float4*)&xn[4] = *(const float4*)(xsrc + 4);
                }
                if (g < NG - 1) {                          // E prefetch (same tile)
                    #pragma unroll
                    for (int k = 0; k < 8; ++k)
                        en[k] = Ecur[((g + 1) * GL + k) * NPB + nl];
                }
                // speculative FADD chain + one-hot first-crossing select
                float A = S, P = 1.0f, T = 0.0f;
                #pragma unroll
                for (int i = 0; i < 8; ++i) {
                    float gk;                                    // [A_{i} > th]
                    asm("set.gt.f32.f32 %0, %1, %2;" : "=f"(gk) : "f"(A), "f"(th));
                    float u = P * gk;                            // one-hot at 1st crossing
                    T = fmaf(u, ex[i], T);                       // pick E_{i+1}
                    P = P - u;                                   // exact 0/1 arithmetic
                    A = A + xg[i];                               // critical chain (FADD)
                }
                S = fmaf(P, A, T);   // exact: P=1 -> A_8 ; P=0 -> E_k
                #pragma unroll
                for (int k = 0; k < 8; ++k) { xg[k] = xn[k]; ex[k] = en[k]; }
            }
        }
        if (wid == 1 && t + 1 < NS)
            do_helpers(xs[(t + 1) & 3], Et[(t + 1) & 1], thr_s, lane);
        if (wid == 2 && t >= 1 && t <= NS)
            do_rerun(xs[(t - 1) & 3], bnd[(t - 1) & 1], sbuf[(t - 1) & 1],
                     thr_s, lane);
        if (wid == 3) {
            if (t + 2 < NS)
                *(float4*)&xs[(t + 2) & 3][lane * 4] =
                    *(const float4*)(xb + (t + 2) * NH + lane * 4);
            if (t >= 2 && t <= NS + 1)
                do_drain(b, q, t - 2, sbuf[(t - 2) & 1], thr_s, outbuf, lane);
        }
        __syncthreads();
    }
}

extern "C" void kernel_launch(void* const* d_in, const int* in_sizes, int n_in,
                              void* d_out, int out_size)
{
    const float* inputs   = (const float*)d_in[0];  // [B,S,H]
    const float* threshes = (const float*)d_in[1];  // [N]
    const float* acc0     = (const float*)d_in[2];  // [B,N]
    float* out = (float*)d_out;                     // outs then spikes (f32)

    lif_kernel<<<NB * 4, 128>>>(inputs, threshes, acc0, out);
}